// round 5
// baseline (speedup 1.0000x reference)
#include <cuda_runtime.h>
#include <math.h>

#define Bn   16
#define Cn   256
#define Hn   128
#define Wn   128
#define HWn  (Hn * Wn)      // 16384
#define Kn   300

// Scratch (allocation-free rule: __device__ globals). 4 MB total -> L2-resident.
__device__ float    g_reg0 [Bn * HWn];
__device__ float    g_reg1 [Bn * HWn];
__device__ float    g_conf [Bn * HWn];
__device__ unsigned g_sbits[Bn * HWn];

// ---------------------------------------------------------------------------
// Pass 1: fused 1x1 convs + sigmoid + score. One thread = 4 pixels (float4).
// 512 blocks x 128 threads = 65536 threads = B*HW/4 groups.
// ---------------------------------------------------------------------------
__global__ __launch_bounds__(128) void score_kernel(
    const float* __restrict__ x,
    const float* __restrict__ w_reg,
    const float* __restrict__ b_reg,
    const float* __restrict__ w_conf,
    const float* __restrict__ b_conf)
{
    __shared__ float wr0[Cn], wr1[Cn], wc[Cn];
    for (int i = threadIdx.x; i < Cn; i += 128) {
        wr0[i] = w_reg[i];
        wr1[i] = w_reg[Cn + i];
        wc[i]  = w_conf[i];
    }
    __syncthreads();

    const int gid = blockIdx.x * 128 + threadIdx.x;     // pixel-group id
    const int b   = gid / (HWn / 4);
    const int g   = gid % (HWn / 4);

    const float4* xp = reinterpret_cast<const float4*>(x)
                       + (size_t)b * Cn * (HWn / 4) + g;

    float4 a0 = make_float4(0.f, 0.f, 0.f, 0.f);
    float4 a1 = make_float4(0.f, 0.f, 0.f, 0.f);
    float4 a2 = make_float4(0.f, 0.f, 0.f, 0.f);

    #pragma unroll 8
    for (int c = 0; c < Cn; ++c) {
        float4 xv = xp[(size_t)c * (HWn / 4)];
        float u0 = wr0[c], u1 = wr1[c], u2 = wc[c];
        a0.x = fmaf(xv.x, u0, a0.x); a0.y = fmaf(xv.y, u0, a0.y);
        a0.z = fmaf(xv.z, u0, a0.z); a0.w = fmaf(xv.w, u0, a0.w);
        a1.x = fmaf(xv.x, u1, a1.x); a1.y = fmaf(xv.y, u1, a1.y);
        a1.z = fmaf(xv.z, u1, a1.z); a1.w = fmaf(xv.w, u1, a1.w);
        a2.x = fmaf(xv.x, u2, a2.x); a2.y = fmaf(xv.y, u2, a2.y);
        a2.z = fmaf(xv.z, u2, a2.z); a2.w = fmaf(xv.w, u2, a2.w);
    }

    const float br0 = __ldg(b_reg), br1 = __ldg(b_reg + 1), bc = __ldg(b_conf);

    float4 r0v, r1v, cfv; uint4 sbv;
    const float* p0 = &a0.x; const float* p1 = &a1.x; const float* p2 = &a2.x;
    float*       q0 = &r0v.x; float*      q1 = &r1v.x; float*      qc = &cfv.x;
    unsigned*    qs = &sbv.x;
    #pragma unroll
    for (int i = 0; i < 4; ++i) {
        float r0 = p0[i] + br0;
        float r1 = p1[i] + br1;
        float cf = 1.0f / (1.0f + expf(-(p2[i] + bc)));
        float sc = sqrtf(fmaf(r0, r0, r1 * r1)) * cf;
        q0[i] = r0; q1[i] = r1; qc[i] = cf; qs[i] = __float_as_uint(sc);
    }

    const int v = b * (HWn / 4) + g;   // float4-granular index
    reinterpret_cast<float4*>(g_reg0)[v]  = r0v;
    reinterpret_cast<float4*>(g_reg1)[v]  = r1v;
    reinterpret_cast<float4*>(g_conf)[v]  = cfv;
    reinterpret_cast<uint4*>(g_sbits)[v]  = sbv;
}

// ---------------------------------------------------------------------------
// Pass 2: per-batch exact top-300 (jax.lax.top_k semantics: descending value,
// ties -> lower index) via 2-level radix select on float bits, then stable
// rank-sort of the ~300-candidate set, then gather + grid add + output.
// ---------------------------------------------------------------------------
__global__ __launch_bounds__(1024) void topk_kernel(float* __restrict__ out)
{
    const int b   = blockIdx.x;
    const int tid = threadIdx.x;
    const unsigned* sb = g_sbits + b * HWn;

    __shared__ unsigned hist[4096];
    __shared__ unsigned chunk[128];
    __shared__ unsigned cbits[1024];
    __shared__ int      cidx [1024];
    __shared__ int      s_bin, s_above, s_cnt;

    // ---- level 1: 1024 bins on bits[31:21] (sign bit is 0: scores >= 0) ----
    for (int i = tid; i < 1024; i += 1024) hist[i] = 0;
    __syncthreads();

    unsigned mybits[16];
    #pragma unroll
    for (int j = 0; j < 16; ++j) {
        mybits[j] = sb[tid + j * 1024];
        atomicAdd(&hist[mybits[j] >> 21], 1u);
    }
    __syncthreads();

    if (tid < 32) {
        unsigned s = 0;
        #pragma unroll
        for (int j = 0; j < 32; ++j) s += hist[tid * 32 + j];
        chunk[tid] = s;
    }
    __syncthreads();
    if (tid == 0) {
        int need = Kn, above = 0, ci = 31;
        for (; ci > 0; --ci) {
            if (above + (int)chunk[ci] >= need) break;
            above += (int)chunk[ci];
        }
        int bin = ci * 32 + 31;
        for (; bin > ci * 32; --bin) {
            if (above + (int)hist[bin] >= need) break;
            above += (int)hist[bin];
        }
        s_bin = bin; s_above = above;
    }
    __syncthreads();
    const int b1     = s_bin;
    const int above1 = s_above;
    __syncthreads();   // everyone has read s_bin/hist results before reuse

    // ---- level 2: 4096 bins on bits[20:9], restricted to bin b1 ----
    for (int i = tid; i < 4096; i += 1024) hist[i] = 0;
    __syncthreads();
    #pragma unroll
    for (int j = 0; j < 16; ++j)
        if ((int)(mybits[j] >> 21) == b1)
            atomicAdd(&hist[(mybits[j] >> 9) & 0xFFFu], 1u);
    __syncthreads();

    if (tid < 128) {
        unsigned s = 0;
        #pragma unroll
        for (int j = 0; j < 32; ++j) s += hist[tid * 32 + j];
        chunk[tid] = s;
    }
    __syncthreads();
    if (tid == 0) {
        int need = Kn - above1, above = 0, ci = 127;
        for (; ci > 0; --ci) {
            if (above + (int)chunk[ci] >= need) break;
            above += (int)chunk[ci];
        }
        int bin = ci * 32 + 31;
        for (; bin > ci * 32; --bin) {
            if (above + (int)hist[bin] >= need) break;
            above += (int)hist[bin];
        }
        s_bin = bin;
        s_cnt = 0;
    }
    __syncthreads();

    // 23-bit threshold: everything >= thr is a candidate (>= 300 of them,
    // typically ~300 + |threshold bin| which is O(1) for continuous data).
    const unsigned thr = ((unsigned)b1 << 21) | ((unsigned)s_bin << 9);

    #pragma unroll
    for (int j = 0; j < 16; ++j) {
        if (mybits[j] >= thr) {
            int p = atomicAdd(&s_cnt, 1);
            if (p < 1024) { cbits[p] = mybits[j]; cidx[p] = tid + j * 1024; }
        }
    }
    __syncthreads();

    const int M = min(s_cnt, 1024);

    // ---- stable rank sort (O(M^2), broadcast SMEM reads) + gather/write ----
    if (tid < M) {
        const unsigned mb = cbits[tid];
        const int      mi = cidx[tid];
        int rank = 0;
        for (int j = 0; j < M; ++j) {
            unsigned ob = cbits[j];
            rank += (ob > mb) || (ob == mb && cidx[j] < mi);
        }
        if (rank < Kn) {
            const int k = mi;
            float* o = out + ((size_t)b * Kn + rank) * 3;
            o[0] = (float)(k / Hn) + g_reg0[b * HWn + k];
            o[1] = (float)(k % Hn) + g_reg1[b * HWn + k];
            o[2] = g_conf[b * HWn + k];
        }
    }
}

// ---------------------------------------------------------------------------
extern "C" void kernel_launch(void* const* d_in, const int* in_sizes, int n_in,
                              void* d_out, int out_size)
{
    const float* x      = (const float*)d_in[0];  // (16,256,128,128)
    const float* w_reg  = (const float*)d_in[1];  // (2,256)
    const float* b_reg  = (const float*)d_in[2];  // (2,)
    const float* w_conf = (const float*)d_in[3];  // (1,256)
    const float* b_conf = (const float*)d_in[4];  // (1,)
    float*       out    = (float*)d_out;          // (16,300,3)

    score_kernel<<<512, 128>>>(x, w_reg, b_reg, w_conf, b_conf);
    topk_kernel<<<Bn, 1024>>>(out);
}

// round 9
// speedup vs baseline: 1.0725x; 1.0725x over previous
#include <cuda_runtime.h>
#include <math.h>

#define Bn   16
#define Cn   256
#define Hn   128
#define Wn   128
#define HWn  (Hn * Wn)      // 16384
#define Kn   300
#define CAP  2048           // candidate capacity (count(>=P) is capped <=1024 by early stop)

// Scratch (allocation-free rule: __device__ globals). 4 MB total -> L2-resident.
__device__ float    g_reg0 [Bn * HWn];
__device__ float    g_reg1 [Bn * HWn];
__device__ float    g_conf [Bn * HWn];
__device__ unsigned g_sbits[Bn * HWn];

// ---------------------------------------------------------------------------
// Pass 1: fused 1x1 convs + sigmoid + score. One thread = 4 pixels (float4).
// 256 blocks x 256 threads = 65536 threads = B*HW/4 groups. HBM-bound.
// ---------------------------------------------------------------------------
__global__ __launch_bounds__(256) void score_kernel(
    const float* __restrict__ x,
    const float* __restrict__ w_reg,
    const float* __restrict__ b_reg,
    const float* __restrict__ w_conf,
    const float* __restrict__ b_conf)
{
    __shared__ float wr0[Cn], wr1[Cn], wc[Cn];
    for (int i = threadIdx.x; i < Cn; i += 256) {
        wr0[i] = w_reg[i];
        wr1[i] = w_reg[Cn + i];
        wc[i]  = w_conf[i];
    }
    __syncthreads();

    const int gid = blockIdx.x * 256 + threadIdx.x;     // pixel-group id
    const int b   = gid / (HWn / 4);
    const int g   = gid % (HWn / 4);

    const float4* xp = reinterpret_cast<const float4*>(x)
                       + (size_t)b * Cn * (HWn / 4) + g;

    float4 a0 = make_float4(0.f, 0.f, 0.f, 0.f);
    float4 a1 = make_float4(0.f, 0.f, 0.f, 0.f);
    float4 a2 = make_float4(0.f, 0.f, 0.f, 0.f);

    #pragma unroll 8
    for (int c = 0; c < Cn; ++c) {
        // evict-first streaming load: don't let the 268MB stream thrash L2
        float4 xv = __ldcs(&xp[(size_t)c * (HWn / 4)]);
        float u0 = wr0[c], u1 = wr1[c], u2 = wc[c];
        a0.x = fmaf(xv.x, u0, a0.x); a0.y = fmaf(xv.y, u0, a0.y);
        a0.z = fmaf(xv.z, u0, a0.z); a0.w = fmaf(xv.w, u0, a0.w);
        a1.x = fmaf(xv.x, u1, a1.x); a1.y = fmaf(xv.y, u1, a1.y);
        a1.z = fmaf(xv.z, u1, a1.z); a1.w = fmaf(xv.w, u1, a1.w);
        a2.x = fmaf(xv.x, u2, a2.x); a2.y = fmaf(xv.y, u2, a2.y);
        a2.z = fmaf(xv.z, u2, a2.z); a2.w = fmaf(xv.w, u2, a2.w);
    }

    const float br0 = __ldg(b_reg), br1 = __ldg(b_reg + 1), bc = __ldg(b_conf);

    float4 r0v, r1v, cfv; uint4 sbv;
    const float* p0 = &a0.x; const float* p1 = &a1.x; const float* p2 = &a2.x;
    float*       q0 = &r0v.x; float*      q1 = &r1v.x; float*      qc = &cfv.x;
    unsigned*    qs = &sbv.x;
    #pragma unroll
    for (int i = 0; i < 4; ++i) {
        float r0 = p0[i] + br0;
        float r1 = p1[i] + br1;
        float cf = 1.0f / (1.0f + expf(-(p2[i] + bc)));
        float sc = sqrtf(fmaf(r0, r0, r1 * r1)) * cf;
        q0[i] = r0; q1[i] = r1; qc[i] = cf; qs[i] = __float_as_uint(sc);
    }

    const int v = b * (HWn / 4) + g;   // float4-granular index
    reinterpret_cast<float4*>(g_reg0)[v]  = r0v;
    reinterpret_cast<float4*>(g_reg1)[v]  = r1v;
    reinterpret_cast<float4*>(g_conf)[v]  = cfv;
    reinterpret_cast<uint4*>(g_sbits)[v]  = sbv;
}

// ---------------------------------------------------------------------------
// Pass 2: per-batch exact top-300 (jax.lax.top_k semantics: descending value,
// ties -> lower index).
//
// Atomic-free MSB-down radix bisection on the float bit pattern (scores>=0 so
// bits order like values): per bit, count(>= trial) via register compares +
// __reduce_add_sync + 32-slot SMEM sum. Raise the threshold whenever >=300
// survive; early-stop once the surviving count <= 1024. Final P satisfies
// 300 <= count(>=P) <= 1024 and P <= v_300, so candidates are an exact
// superset of the top-300. Then stable O(M^2) rank sort on 64-bit composite
// keys (bits<<32 | HWn-idx) encodes the tie rule as a single compare.
// ---------------------------------------------------------------------------
__global__ __launch_bounds__(1024) void topk_kernel(float* __restrict__ out)
{
    const int b    = blockIdx.x;
    const int tid  = threadIdx.x;
    const int wid  = tid >> 5;
    const int lane = tid & 31;
    const unsigned* sb = g_sbits + b * HWn;

    __shared__ int      wcnt[32];
    __shared__ unsigned s_P;
    __shared__ int      s_cnt, s_done, s_m;
    __shared__ unsigned long long ckey[CAP];

    unsigned v[16];
    #pragma unroll
    for (int j = 0; j < 16; ++j) v[j] = sb[tid + j * 1024];

    if (tid == 0) { s_P = 0u; s_done = 0; s_m = 0; s_cnt = HWn; }
    __syncthreads();

    for (int bit = 30; bit >= 0; --bit) {
        const unsigned T = s_P | (1u << bit);
        int c = 0;
        #pragma unroll
        for (int j = 0; j < 16; ++j) c += (v[j] >= T);
        c = __reduce_add_sync(0xFFFFFFFFu, c);
        if (lane == 0) wcnt[wid] = c;
        __syncthreads();
        if (tid == 0) {
            int tot = 0;
            #pragma unroll
            for (int i = 0; i < 32; ++i) tot += wcnt[i];
            if (tot >= Kn) { s_P = T; s_cnt = tot; }   // keep invariant cnt>=K
            if (s_cnt <= 1024) s_done = 1;             // small enough: stop
        }
        __syncthreads();
        if (s_done) break;
    }

    // ---- collect candidates (>= P). ptxas warp-aggregates the counter. ----
    const unsigned P = s_P;
    #pragma unroll
    for (int j = 0; j < 16; ++j) {
        if (v[j] >= P) {
            int p = atomicAdd(&s_m, 1);
            if (p < CAP) {
                const int idx = tid + j * 1024;
                ckey[p] = ((unsigned long long)v[j] << 32)
                        | (unsigned)(HWn - idx);       // smaller idx => bigger key
            }
        }
    }
    __syncthreads();
    const int M = min(s_m, CAP);

    // ---- stable rank sort (broadcast SMEM reads) + gather + write ----
    for (int i = tid; i < M; i += 1024) {
        const unsigned long long mk = ckey[i];
        int rank = 0;
        for (int j = 0; j < M; ++j) rank += (ckey[j] > mk);
        if (rank < Kn) {
            const int k = HWn - (int)(mk & 0xFFFFFFFFu);
            float* o = out + ((size_t)b * Kn + rank) * 3;
            o[0] = (float)(k / Hn) + g_reg0[b * HWn + k];
            o[1] = (float)(k % Hn) + g_reg1[b * HWn + k];
            o[2] = g_conf[b * HWn + k];
        }
    }
}

// ---------------------------------------------------------------------------
extern "C" void kernel_launch(void* const* d_in, const int* in_sizes, int n_in,
                              void* d_out, int out_size)
{
    const float* x      = (const float*)d_in[0];  // (16,256,128,128)
    const float* w_reg  = (const float*)d_in[1];  // (2,256)
    const float* b_reg  = (const float*)d_in[2];  // (2,)
    const float* w_conf = (const float*)d_in[3];  // (1,256)
    const float* b_conf = (const float*)d_in[4];  // (1,)
    float*       out    = (float*)d_out;          // (16,300,3)

    score_kernel<<<256, 256>>>(x, w_reg, b_reg, w_conf, b_conf);
    topk_kernel<<<Bn, 1024>>>(out);
}

// round 10
// speedup vs baseline: 1.1306x; 1.0541x over previous
#include <cuda_runtime.h>
#include <math.h>

#define Bn   16
#define Cn   256
#define Hn   128
#define Wn   128
#define HWn  (Hn * Wn)      // 16384
#define Kn   300
#define CAP  1024           // candidate capacity
#define STOPC 400           // bisection early-stop count (sort cost ~ M^2)

// Scratch (allocation-free rule: __device__ globals). 4 MB total -> L2-resident.
__device__ float    g_reg0 [Bn * HWn];
__device__ float    g_reg1 [Bn * HWn];
__device__ float    g_conf [Bn * HWn];
__device__ unsigned g_sbits[Bn * HWn];

// ---------------------------------------------------------------------------
// Pass 1: fused 1x1 convs + sigmoid + score. One thread = 4 pixels (float4).
// grid 128 x 512 = 65536 threads = B*HW/4 groups: ONE perfectly balanced wave
// (128 SMs, no ragged second wave). HBM-bound.
// ---------------------------------------------------------------------------
__global__ __launch_bounds__(512) void score_kernel(
    const float* __restrict__ x,
    const float* __restrict__ w_reg,
    const float* __restrict__ b_reg,
    const float* __restrict__ w_conf,
    const float* __restrict__ b_conf)
{
    __shared__ float wr0[Cn], wr1[Cn], wc[Cn];
    for (int i = threadIdx.x; i < Cn; i += 512) {
        wr0[i] = w_reg[i];
        wr1[i] = w_reg[Cn + i];
        wc[i]  = w_conf[i];
    }
    __syncthreads();

    const int gid = blockIdx.x * 512 + threadIdx.x;     // pixel-group id
    const int b   = gid >> 12;                          // / (HWn/4)
    const int g   = gid & 4095;                         // % (HWn/4)

    const float4* xp = reinterpret_cast<const float4*>(x)
                       + (size_t)b * Cn * (HWn / 4) + g;

    float4 a0 = make_float4(0.f, 0.f, 0.f, 0.f);
    float4 a1 = make_float4(0.f, 0.f, 0.f, 0.f);
    float4 a2 = make_float4(0.f, 0.f, 0.f, 0.f);

    #pragma unroll 8
    for (int c = 0; c < Cn; ++c) {
        // evict-first streaming load: don't thrash L2 (scratch lives there)
        float4 xv = __ldcs(&xp[(size_t)c * (HWn / 4)]);
        float u0 = wr0[c], u1 = wr1[c], u2 = wc[c];
        a0.x = fmaf(xv.x, u0, a0.x); a0.y = fmaf(xv.y, u0, a0.y);
        a0.z = fmaf(xv.z, u0, a0.z); a0.w = fmaf(xv.w, u0, a0.w);
        a1.x = fmaf(xv.x, u1, a1.x); a1.y = fmaf(xv.y, u1, a1.y);
        a1.z = fmaf(xv.z, u1, a1.z); a1.w = fmaf(xv.w, u1, a1.w);
        a2.x = fmaf(xv.x, u2, a2.x); a2.y = fmaf(xv.y, u2, a2.y);
        a2.z = fmaf(xv.z, u2, a2.z); a2.w = fmaf(xv.w, u2, a2.w);
    }

    const float br0 = __ldg(b_reg), br1 = __ldg(b_reg + 1), bc = __ldg(b_conf);

    float4 r0v, r1v, cfv; uint4 sbv;
    const float* p0 = &a0.x; const float* p1 = &a1.x; const float* p2 = &a2.x;
    float*       q0 = &r0v.x; float*      q1 = &r1v.x; float*      qc = &cfv.x;
    unsigned*    qs = &sbv.x;
    #pragma unroll
    for (int i = 0; i < 4; ++i) {
        float r0 = p0[i] + br0;
        float r1 = p1[i] + br1;
        float cf = 1.0f / (1.0f + expf(-(p2[i] + bc)));
        float sc = sqrtf(fmaf(r0, r0, r1 * r1)) * cf;
        q0[i] = r0; q1[i] = r1; qc[i] = cf; qs[i] = __float_as_uint(sc);
    }

    const int v = b * (HWn / 4) + g;   // float4-granular index
    reinterpret_cast<float4*>(g_reg0)[v]  = r0v;
    reinterpret_cast<float4*>(g_reg1)[v]  = r1v;
    reinterpret_cast<float4*>(g_conf)[v]  = cfv;
    reinterpret_cast<uint4*>(g_sbits)[v]  = sbv;
}

// ---------------------------------------------------------------------------
// Pass 2: per-batch exact top-300 (jax.lax.top_k semantics: descending value,
// ties -> lower index).
//
// MSB-down radix bisection on non-negative float bit patterns: per bit, count
// (>= trial) via register compares + __reduce_add_sync + 16-slot warp-0
// reduce. Accept when >= 300 survive; keep refining until the accepted count
// <= STOPC so the O(M^2) rank sort stays cheap (sort cost ~ M^2 and each
// extra bisection iter is only ~500 cyc). Final P <= v_300, so candidates are
// an exact superset of the top-300. Stable tie rule encoded in 64-bit keys
// (bits<<32 | HWn-idx): one compare per pair.
// ---------------------------------------------------------------------------
__global__ __launch_bounds__(512) void topk_kernel(float* __restrict__ out)
{
    const int b    = blockIdx.x;
    const int tid  = threadIdx.x;
    const int wid  = tid >> 5;
    const int lane = tid & 31;
    const unsigned* sb = g_sbits + b * HWn;

    __shared__ int      wcnt[16];
    __shared__ unsigned s_P;
    __shared__ int      s_done, s_m;
    __shared__ unsigned long long ckey[CAP];

    unsigned v[32];
    #pragma unroll
    for (int j = 0; j < 32; ++j) v[j] = sb[tid + j * 512];

    if (tid == 0) { s_P = 0u; s_done = 0; s_m = 0; }
    __syncthreads();

    unsigned P = 0u;
    for (int bit = 30; bit >= 0; --bit) {
        const unsigned T = P | (1u << bit);
        int c = 0;
        #pragma unroll
        for (int j = 0; j < 32; ++j) c += (v[j] >= T);
        c = __reduce_add_sync(0xFFFFFFFFu, c);
        if (lane == 0) wcnt[wid] = c;
        __syncthreads();
        if (wid == 0) {
            int t = (lane < 16) ? wcnt[lane] : 0;
            t = __reduce_add_sync(0xFFFFFFFFu, t);
            if (lane == 0 && t >= Kn) {
                s_P = T;                       // accept: invariant cnt >= K
                if (t <= STOPC) s_done = 1;    // small enough for cheap sort
            }
        }
        __syncthreads();
        P = s_P;
        if (s_done) break;
        __syncthreads();   // protect wcnt reuse next iteration
    }

    // ---- collect candidates (>= P); warp-aggregated atomic counter ----
    #pragma unroll
    for (int j = 0; j < 32; ++j) {
        if (v[j] >= P) {
            int p = atomicAdd(&s_m, 1);
            if (p < CAP) {
                const int idx = tid + j * 512;
                ckey[p] = ((unsigned long long)v[j] << 32)
                        | (unsigned)(HWn - idx);       // smaller idx => bigger key
            }
        }
    }
    __syncthreads();
    const int M = min(s_m, CAP);

    // ---- stable rank sort (broadcast SMEM reads) + gather + write ----
    for (int i = tid; i < M; i += 512) {
        const unsigned long long mk = ckey[i];
        int rank = 0;
        #pragma unroll 4
        for (int j = 0; j < M; ++j) rank += (ckey[j] > mk);
        if (rank < Kn) {
            const int k = HWn - (int)(mk & 0xFFFFFFFFu);
            float* o = out + ((size_t)b * Kn + rank) * 3;
            o[0] = (float)(k / Hn) + g_reg0[b * HWn + k];
            o[1] = (float)(k % Hn) + g_reg1[b * HWn + k];
            o[2] = g_conf[b * HWn + k];
        }
    }
}

// ---------------------------------------------------------------------------
extern "C" void kernel_launch(void* const* d_in, const int* in_sizes, int n_in,
                              void* d_out, int out_size)
{
    const float* x      = (const float*)d_in[0];  // (16,256,128,128)
    const float* w_reg  = (const float*)d_in[1];  // (2,256)
    const float* b_reg  = (const float*)d_in[2];  // (2,)
    const float* w_conf = (const float*)d_in[3];  // (1,256)
    const float* b_conf = (const float*)d_in[4];  // (1,)
    float*       out    = (float*)d_out;          // (16,300,3)

    score_kernel<<<128, 512>>>(x, w_reg, b_reg, w_conf, b_conf);
    topk_kernel<<<Bn, 512>>>(out);
}